// round 12
// baseline (speedup 1.0000x reference)
#include <cuda_runtime.h>
#include <cuda_bf16.h>

// Embedding gather: out[i, :] = table[ids[i], :]
// ids: int32 [819200], table: f32 [1e6, 32] (~128 MB; touched ~72 MB, L2-resident),
// out: f32 [819200, 32]
//
// Final configuration:
//  - table loads: L2::evict_last policy + L1::no_allocate (zero L1 reuse)
//  - output stores: .cs streaming (evict-first; don't displace the table in L2)
//  - 4 independent row-gathers per thread (MLP sweet spot; 2/8/v8/wt all worse)
//  - warp-dedup id loads via shfl, branchless (all lanes load with lane&15;
//    duplicates broadcast-coalesce, no divergent branch in front of the shuffles)

#define NSEG 4

__device__ __forceinline__ float4 ldg_table(const float4* p, unsigned long long pol) {
    float4 v;
    asm volatile("ld.global.nc.L1::no_allocate.L2::cache_hint.v4.f32 {%0,%1,%2,%3}, [%4], %5;"
                 : "=f"(v.x), "=f"(v.y), "=f"(v.z), "=f"(v.w)
                 : "l"(p), "l"(pol));
    return v;
}

__device__ __forceinline__ void stg_stream(float4* p, float4 v) {
    asm volatile("st.global.cs.v4.f32 [%0], {%1,%2,%3,%4};"
                 :: "l"(p), "f"(v.x), "f"(v.y), "f"(v.z), "f"(v.w)
                 : "memory");
}

__global__ void __launch_bounds__(256)
embedding_gather_kernel(const int* __restrict__ ids,
                        const float4* __restrict__ table4,
                        float4* __restrict__ out4,
                        int seg) {
    int warp_base = blockIdx.x * blockDim.x + (threadIdx.x & ~31);
    int lane = threadIdx.x & 31;
    int i = warp_base + lane;
    if (i >= seg) return;   // seg = 1,638,400 / 4 ... grid sized so whole warps pass

    unsigned long long pol;
    asm volatile("createpolicy.fractional.L2::evict_last.b64 %0, 1.0;" : "=l"(pol));

    // Branchless warp-dedup id load: 16 distinct ids per warp-iteration.
    // Lane l loads id #(l & 15); lanes 16..31 duplicate 0..15 (broadcast-coalesced).
    int l16 = lane & 15;
    int s16 = l16 >> 2;                                   // segment 0..3
    int r   = ((warp_base + s16 * seg) >> 3) + (l16 & 3); // id row
    int my_id = __ldg(&ids[r]);

    int idx[NSEG];
    int id[NSEG];
#pragma unroll
    for (int s = 0; s < NSEG; s++) {
        idx[s] = i + s * seg;
        id[s]  = __shfl_sync(0xffffffffu, my_id, s * 4 + (lane >> 3));
    }

    float4 v[NSEG];
#pragma unroll
    for (int s = 0; s < NSEG; s++)
        v[s] = ldg_table(&table4[(size_t)(unsigned)id[s] * 8 + (idx[s] & 7)], pol);

#pragma unroll
    for (int s = 0; s < NSEG; s++)
        stg_stream(&out4[idx[s]], v[s]);
}

extern "C" void kernel_launch(void* const* d_in, const int* in_sizes, int n_in,
                              void* d_out, int out_size) {
    // Resolve inputs by element count (table: 32,000,000 f32; ids: 819,200).
    const int*    ids;
    const float4* table;
    int n_rows;
    if (in_sizes[0] > in_sizes[1]) {
        table = (const float4*)d_in[0];
        ids   = (const int*)d_in[1];
        n_rows = in_sizes[1];
    } else {
        ids   = (const int*)d_in[0];
        table = (const float4*)d_in[1];
        n_rows = in_sizes[0];
    }

    float4* out = (float4*)d_out;
    int n4 = n_rows * 8;          // total float4 elements (divisible by NSEG)
    int seg = n4 / NSEG;          // 1,638,400 = 256 * 6400 (whole warps/blocks)
    int threads = 256;
    int blocks = (seg + threads - 1) / threads;
    embedding_gather_kernel<<<blocks, threads>>>(ids, table, out, seg);
}

// round 13
// speedup vs baseline: 1.0135x; 1.0135x over previous
#include <cuda_runtime.h>
#include <cuda_bf16.h>

// Embedding gather: out[i, :] = table[ids[i], :]
// ids: int32 [819200], table: f32 [1e6, 32] (~128 MB; touched ~72 MB, L2-resident),
// out: f32 [819200, 32]
//
// Final configuration (best of 12 rounds, 33.28 us bench; baseline was 45.1):
//  - table loads: L2::evict_last policy (rows stay L2-resident across graph
//    replays) + L1::no_allocate (random 128B rows have ~0 L1 reuse)
//  - output stores: .cs streaming (evict-first; write-once output doesn't
//    displace the table in L2)
//  - 4 independent row-gathers per thread (MLP sweet spot; 2/8/v8/wt all worse)
//  - warp-dedup id loads: lanes 0..15 load the warp's 16 distinct ids once
//    (predicated; a predicated-off LDG is free), distributed via shfl

#define NSEG 4

__device__ __forceinline__ float4 ldg_table(const float4* p, unsigned long long pol) {
    float4 v;
    asm volatile("ld.global.nc.L1::no_allocate.L2::cache_hint.v4.f32 {%0,%1,%2,%3}, [%4], %5;"
                 : "=f"(v.x), "=f"(v.y), "=f"(v.z), "=f"(v.w)
                 : "l"(p), "l"(pol));
    return v;
}

__device__ __forceinline__ void stg_stream(float4* p, float4 v) {
    asm volatile("st.global.cs.v4.f32 [%0], {%1,%2,%3,%4};"
                 :: "l"(p), "f"(v.x), "f"(v.y), "f"(v.z), "f"(v.w)
                 : "memory");
}

__global__ void __launch_bounds__(256)
embedding_gather_kernel(const int* __restrict__ ids,
                        const float4* __restrict__ table4,
                        float4* __restrict__ out4,
                        int seg) {
    int warp_base = blockIdx.x * blockDim.x + (threadIdx.x & ~31);
    int lane = threadIdx.x & 31;
    int i = warp_base + lane;
    if (i >= seg) return;   // seg = 1,638,400 = 256*6400: whole warps uniformly pass

    unsigned long long pol;
    asm volatile("createpolicy.fractional.L2::evict_last.b64 %0, 1.0;" : "=l"(pol));

    // Lanes 0..15 load the warp's 16 distinct ids:
    // lane l -> segment (l>>2), row offset (l&3) within that segment's 4-row span.
    int my_id = 0;
    if (lane < 16) {
        int s = lane >> 2;
        int r = ((warp_base + s * seg) >> 3) + (lane & 3);
        my_id = __ldg(&ids[r]);
    }

    int idx[NSEG];
    int id[NSEG];
#pragma unroll
    for (int s = 0; s < NSEG; s++) {
        idx[s] = i + s * seg;
        // source lane holding ids[(warp_base + s*seg)>>3 + (lane>>3)]
        id[s] = __shfl_sync(0xffffffffu, my_id, s * 4 + (lane >> 3));
    }

    float4 v[NSEG];
#pragma unroll
    for (int s = 0; s < NSEG; s++)
        v[s] = ldg_table(&table4[(size_t)(unsigned)id[s] * 8 + (idx[s] & 7)], pol);

#pragma unroll
    for (int s = 0; s < NSEG; s++)
        stg_stream(&out4[idx[s]], v[s]);
}

extern "C" void kernel_launch(void* const* d_in, const int* in_sizes, int n_in,
                              void* d_out, int out_size) {
    // Resolve inputs by element count (table: 32,000,000 f32; ids: 819,200).
    const int*    ids;
    const float4* table;
    int n_rows;
    if (in_sizes[0] > in_sizes[1]) {
        table = (const float4*)d_in[0];
        ids   = (const int*)d_in[1];
        n_rows = in_sizes[1];
    } else {
        ids   = (const int*)d_in[0];
        table = (const float4*)d_in[1];
        n_rows = in_sizes[0];
    }

    float4* out = (float4*)d_out;
    int n4 = n_rows * 8;          // total float4 elements (divisible by NSEG)
    int seg = n4 / NSEG;          // 1,638,400 = 256 * 6400 (whole warps/blocks)
    int threads = 256;
    int blocks = (seg + threads - 1) / threads;
    embedding_gather_kernel<<<blocks, threads>>>(ids, table, out, seg);
}